// round 2
// baseline (speedup 1.0000x reference)
#include <cuda_runtime.h>
#include <cuda_bf16.h>

// AssociativeLIF: x (B=32, T=128, N=4096) fp32
//   i_syn[t] = 0.5 * i_syn[t-1] + x[t]
//   v[t]     = tau * v[t-1] + (1 - tau) * i_syn[t]
//   spike[t] = (v[t] >= thr) ? 1.0f : 0.0f
// tau = clip(tau_mem, 0.8, 0.98), thr = clip(v_threshold, 0.05, 0.5), per-neuron.
//
// Memory-bound: one thread per (b, n-quad), sequential walk over T with
// 8-deep load batching for MLP.

#define B_DIM 32
#define T_DIM 128
#define N_DIM 4096
#define N4 (N_DIM / 4)          // 1024
#define THREADS 128
#define TOTAL_THREADS (B_DIM * N4)  // 32768
#define UNROLL 8

__global__ __launch_bounds__(THREADS, 8)
void lif_kernel(const float4* __restrict__ x,
                const float4* __restrict__ tau_mem,
                const float4* __restrict__ vthr,
                float4* __restrict__ out)
{
    const int idx = blockIdx.x * THREADS + threadIdx.x;   // 0 .. 32767
    const int n4  = idx & (N4 - 1);                       // quad index within N
    const int b   = idx >> 10;                            // N4 == 1024

    // per-neuron params (coalesced float4 loads), clamped like the reference
    float4 tm = tau_mem[n4];
    float4 th = vthr[n4];

    const float tax = fminf(fmaxf(tm.x, 0.8f), 0.98f);
    const float tay = fminf(fmaxf(tm.y, 0.8f), 0.98f);
    const float taz = fminf(fmaxf(tm.z, 0.8f), 0.98f);
    const float taw = fminf(fmaxf(tm.w, 0.8f), 0.98f);

    const float omx = 1.0f - tax;
    const float omy = 1.0f - tay;
    const float omz = 1.0f - taz;
    const float omw = 1.0f - taw;

    const float thx = fminf(fmaxf(th.x, 0.05f), 0.5f);
    const float thy = fminf(fmaxf(th.y, 0.05f), 0.5f);
    const float thz = fminf(fmaxf(th.z, 0.05f), 0.5f);
    const float thw = fminf(fmaxf(th.w, 0.05f), 0.5f);

    const size_t base = (size_t)b * T_DIM * N4 + n4;
    const float4* __restrict__ xp = x + base;
    float4* __restrict__ op = out + base;

    float ix = 0.f, iy = 0.f, iz = 0.f, iw = 0.f;   // i_syn
    float vx = 0.f, vy = 0.f, vz = 0.f, vw = 0.f;   // v_mem

    #pragma unroll 1
    for (int t0 = 0; t0 < T_DIM; t0 += UNROLL) {
        // batch 8 independent loads up front -> MLP=8 per warp
        float4 xs[UNROLL];
        #pragma unroll
        for (int u = 0; u < UNROLL; ++u)
            xs[u] = xp[(size_t)(t0 + u) * N4];

        #pragma unroll
        for (int u = 0; u < UNROLL; ++u) {
            // synaptic current
            ix = fmaf(0.5f, ix, xs[u].x);
            iy = fmaf(0.5f, iy, xs[u].y);
            iz = fmaf(0.5f, iz, xs[u].z);
            iw = fmaf(0.5f, iw, xs[u].w);

            // membrane: b_t = (1-tau)*i computed separately (matches the
            // reference's elementwise (1-tau)*i_syn), then v = tau*v + b_t
            vx = fmaf(tax, vx, __fmul_rn(omx, ix));
            vy = fmaf(tay, vy, __fmul_rn(omy, iy));
            vz = fmaf(taz, vz, __fmul_rn(omz, iz));
            vw = fmaf(taw, vw, __fmul_rn(omw, iw));

            float4 s;
            s.x = (vx >= thx) ? 1.0f : 0.0f;
            s.y = (vy >= thy) ? 1.0f : 0.0f;
            s.z = (vz >= thz) ? 1.0f : 0.0f;
            s.w = (vw >= thw) ? 1.0f : 0.0f;
            op[(size_t)(t0 + u) * N4] = s;
        }
    }
}

extern "C" void kernel_launch(void* const* d_in, const int* in_sizes, int n_in,
                              void* d_out, int out_size)
{
    const float4* x   = (const float4*)d_in[0];
    const float4* tau = (const float4*)d_in[1];
    const float4* thr = (const float4*)d_in[2];
    float4* out = (float4*)d_out;

    dim3 grid(TOTAL_THREADS / THREADS);   // 256 blocks
    dim3 block(THREADS);                  // 128 threads
    lif_kernel<<<grid, block>>>(x, tau, thr, out);
}

// round 3
// speedup vs baseline: 1.0768x; 1.0768x over previous
#include <cuda_runtime.h>
#include <cuda_bf16.h>

// AssociativeLIF: x (B=32, T=128, N=4096) fp32
//   i_syn[t] = 0.5 * i_syn[t-1] + x[t]
//   v[t]     = tau * v[t-1] + (1 - tau) * i_syn[t]
//   spike[t] = (v[t] >= thr) ? 1.0f : 0.0f
// tau = clip(tau_mem, 0.8, 0.98), thr = clip(v_threshold, 0.05, 0.5) per neuron.
//
// Scalar mapping: one thread per (b, n) -> 131072 threads, 4x the warps of the
// float4 version. Same bytes, far better issue/latency hiding.

#define B_DIM 32
#define T_DIM 128
#define N_DIM 4096
#define THREADS 256
#define TOTAL_THREADS (B_DIM * N_DIM)   // 131072
#define UNROLL 8

__global__ __launch_bounds__(THREADS, 8)
void lif_kernel(const float* __restrict__ x,
                const float* __restrict__ tau_mem,
                const float* __restrict__ vthr,
                float* __restrict__ out)
{
    const int idx = blockIdx.x * THREADS + threadIdx.x;   // 0 .. 131071
    const int n   = idx & (N_DIM - 1);                    // neuron index
    const int b   = idx >> 12;                            // N_DIM == 4096

    // per-neuron params (coalesced), clamped like the reference
    const float tau = fminf(fmaxf(tau_mem[n], 0.8f), 0.98f);
    const float omt = 1.0f - tau;
    const float thr = fminf(fmaxf(vthr[n], 0.05f), 0.5f);

    const size_t base = (size_t)b * T_DIM * N_DIM + n;
    const float* __restrict__ xp = x + base;
    float* __restrict__ op = out + base;

    float isyn = 0.f;
    float v    = 0.f;

    #pragma unroll 1
    for (int t0 = 0; t0 < T_DIM; t0 += UNROLL) {
        // batch UNROLL independent loads up front -> MLP per thread = 8
        float xs[UNROLL];
        #pragma unroll
        for (int u = 0; u < UNROLL; ++u)
            xs[u] = xp[(size_t)(t0 + u) * N_DIM];

        float ss[UNROLL];
        #pragma unroll
        for (int u = 0; u < UNROLL; ++u) {
            isyn = fmaf(0.5f, isyn, xs[u]);
            v    = fmaf(tau, v, __fmul_rn(omt, isyn));
            ss[u] = (v >= thr) ? 1.0f : 0.0f;
        }

        #pragma unroll
        for (int u = 0; u < UNROLL; ++u)
            op[(size_t)(t0 + u) * N_DIM] = ss[u];
    }
}

extern "C" void kernel_launch(void* const* d_in, const int* in_sizes, int n_in,
                              void* d_out, int out_size)
{
    const float* x   = (const float*)d_in[0];
    const float* tau = (const float*)d_in[1];
    const float* thr = (const float*)d_in[2];
    float* out = (float*)d_out;

    dim3 grid(TOTAL_THREADS / THREADS);   // 512 blocks
    dim3 block(THREADS);                  // 256 threads
    lif_kernel<<<grid, block>>>(x, tau, thr, out);
}

// round 4
// speedup vs baseline: 1.2526x; 1.1633x over previous
#include <cuda_runtime.h>
#include <cuda_bf16.h>

// AssociativeLIF: x (B=32, T=128, N=4096) fp32
//   i_syn[t] = 0.5 * i_syn[t-1] + x[t]
//   v[t]     = tau * v[t-1] + (1 - tau) * i_syn[t]
//   spike[t] = (v[t] >= thr) ? 1.0f : 0.0f
// tau = clip(tau_mem, 0.8, 0.98), thr = clip(v_threshold, 0.05, 0.5) per neuron.
//
// Scalar mapping (1 thread per (b,n)), UNROLL=16 with software-pipelined
// double buffering so LDGs for the next batch are in flight while the
// current batch computes/stores -> continuous MLP instead of bursty.

#define B_DIM 32
#define T_DIM 128
#define N_DIM 4096
#define THREADS 256
#define TOTAL_THREADS (B_DIM * N_DIM)   // 131072
#define UNROLL 16

__global__ __launch_bounds__(THREADS, 3)
void lif_kernel(const float* __restrict__ x,
                const float* __restrict__ tau_mem,
                const float* __restrict__ vthr,
                float* __restrict__ out)
{
    const int idx = blockIdx.x * THREADS + threadIdx.x;   // 0 .. 131071
    const int n   = idx & (N_DIM - 1);                    // neuron index
    const int b   = idx >> 12;                            // N_DIM == 4096

    const float tau = fminf(fmaxf(tau_mem[n], 0.8f), 0.98f);
    const float omt = 1.0f - tau;
    const float thr = fminf(fmaxf(vthr[n], 0.05f), 0.5f);

    const size_t base = (size_t)b * T_DIM * N_DIM + n;
    const float* __restrict__ xp = x + base;
    float* __restrict__ op = out + base;

    float isyn = 0.f;
    float v    = 0.f;

    // prologue: fill buffer 0
    float cur[UNROLL];
    #pragma unroll
    for (int u = 0; u < UNROLL; ++u)
        cur[u] = xp[(size_t)u * N_DIM];

    #pragma unroll
    for (int t0 = 0; t0 < T_DIM; t0 += UNROLL) {
        // prefetch next batch FIRST so its loads overlap this batch's compute
        float nxt[UNROLL];
        if (t0 + UNROLL < T_DIM) {
            #pragma unroll
            for (int u = 0; u < UNROLL; ++u)
                nxt[u] = xp[(size_t)(t0 + UNROLL + u) * N_DIM];
        }

        // compute + store current batch (stores interleaved with FMA chain)
        #pragma unroll
        for (int u = 0; u < UNROLL; ++u) {
            isyn = fmaf(0.5f, isyn, cur[u]);
            v    = fmaf(tau, v, __fmul_rn(omt, isyn));
            op[(size_t)(t0 + u) * N_DIM] = (v >= thr) ? 1.0f : 0.0f;
        }

        if (t0 + UNROLL < T_DIM) {
            #pragma unroll
            for (int u = 0; u < UNROLL; ++u)
                cur[u] = nxt[u];
        }
    }
}

extern "C" void kernel_launch(void* const* d_in, const int* in_sizes, int n_in,
                              void* d_out, int out_size)
{
    const float* x   = (const float*)d_in[0];
    const float* tau = (const float*)d_in[1];
    const float* thr = (const float*)d_in[2];
    float* out = (float*)d_out;

    dim3 grid(TOTAL_THREADS / THREADS);   // 512 blocks
    dim3 block(THREADS);                  // 256 threads
    lif_kernel<<<grid, block>>>(x, tau, thr, out);
}

// round 5
// speedup vs baseline: 1.2558x; 1.0026x over previous
#include <cuda_runtime.h>
#include <cuda_bf16.h>

// AssociativeLIF: x (B=32, T=128, N=4096) fp32
//   i_syn[t] = 0.5 * i_syn[t-1] + x[t]
//   v[t]     = tau * v[t-1] + (1 - tau) * i_syn[t]
//   spike[t] = (v[t] >= thr) ? 1.0f : 0.0f
// tau = clip(tau_mem, 0.8, 0.98), thr = clip(v_threshold, 0.05, 0.5) per neuron.
//
// Scalar mapping (1 thread per (b,n)), UNROLL=8 software-pipelined double
// buffer. Registers capped to 64 (launch_bounds 256,4) so all 512 CTAs are
// resident in a single wave (4 CTAs/SM * 148 SM = 592 >= 512) -> no tail.
// Streaming cache hints: x is read once (__ldcs), spikes written once (__stcs).

#define B_DIM 32
#define T_DIM 128
#define N_DIM 4096
#define THREADS 256
#define TOTAL_THREADS (B_DIM * N_DIM)   // 131072
#define UNROLL 8

__global__ __launch_bounds__(THREADS, 4)
void lif_kernel(const float* __restrict__ x,
                const float* __restrict__ tau_mem,
                const float* __restrict__ vthr,
                float* __restrict__ out)
{
    const int idx = blockIdx.x * THREADS + threadIdx.x;   // 0 .. 131071
    const int n   = idx & (N_DIM - 1);                    // neuron index
    const int b   = idx >> 12;                            // N_DIM == 4096

    const float tau = fminf(fmaxf(tau_mem[n], 0.8f), 0.98f);
    const float omt = 1.0f - tau;
    const float thr = fminf(fmaxf(vthr[n], 0.05f), 0.5f);

    const size_t base = (size_t)b * T_DIM * N_DIM + n;
    const float* __restrict__ xp = x + base;
    float* __restrict__ op = out + base;

    float isyn = 0.f;
    float v    = 0.f;

    // prologue: fill buffer 0 (streaming loads: x is read exactly once)
    float cur[UNROLL];
    #pragma unroll
    for (int u = 0; u < UNROLL; ++u)
        cur[u] = __ldcs(xp + (size_t)u * N_DIM);

    #pragma unroll
    for (int t0 = 0; t0 < T_DIM; t0 += UNROLL) {
        // prefetch next batch FIRST so its loads overlap this batch's compute
        float nxt[UNROLL];
        if (t0 + UNROLL < T_DIM) {
            #pragma unroll
            for (int u = 0; u < UNROLL; ++u)
                nxt[u] = __ldcs(xp + (size_t)(t0 + UNROLL + u) * N_DIM);
        }

        // compute + store current batch (stores interleaved with FMA chain)
        #pragma unroll
        for (int u = 0; u < UNROLL; ++u) {
            isyn = fmaf(0.5f, isyn, cur[u]);
            v    = fmaf(tau, v, __fmul_rn(omt, isyn));
            __stcs(op + (size_t)(t0 + u) * N_DIM, (v >= thr) ? 1.0f : 0.0f);
        }

        if (t0 + UNROLL < T_DIM) {
            #pragma unroll
            for (int u = 0; u < UNROLL; ++u)
                cur[u] = nxt[u];
        }
    }
}

extern "C" void kernel_launch(void* const* d_in, const int* in_sizes, int n_in,
                              void* d_out, int out_size)
{
    const float* x   = (const float*)d_in[0];
    const float* tau = (const float*)d_in[1];
    const float* thr = (const float*)d_in[2];
    float* out = (float*)d_out;

    dim3 grid(TOTAL_THREADS / THREADS);   // 512 blocks, one wave
    dim3 block(THREADS);                  // 256 threads
    lif_kernel<<<grid, block>>>(x, tau, thr, out);
}